// round 5
// baseline (speedup 1.0000x reference)
#include <cuda_runtime.h>

// DfOp: complex order-5 causal FIR on first 96 freq bins, copy the rest.
// spec: (B=8, T=3000, F=481, 2) f32 ; coef: (B=8, T=3000, 96, 10) f32
//
// R5 = R4 (winning structure) + streaming cache hints on all single-use
// traffic (coef loads, copy loads/stores) so L2 stays reserved for the
// 5x-reused DF tap lines. DF math unchanged.

#define T_DIM 3000
#define F_DIM 481
#define NDF   96
#define NO    5

__global__ __launch_bounds__(256) void df_kernel(
    const float* __restrict__ spec,
    const float* __restrict__ coef,
    float* __restrict__ out)
{
    const int bt = blockIdx.x;          // row = b*T + t
    const int t  = bt % T_DIM;

    const float2* __restrict__ spec2 = reinterpret_cast<const float2*>(spec);
    const float4* __restrict__ spec4 = reinterpret_cast<const float4*>(spec);
    float2* __restrict__ out2 = reinterpret_cast<float2*>(out);
    float4* __restrict__ out4 = reinterpret_cast<float4*>(out);

    const size_t row = (size_t)bt * F_DIM;     // float2 units
    const int tid = threadIdx.x;

    if (tid < NDF) {
        // ---- DF path: one bin per thread ----
        const int f = tid;
        const float2* __restrict__ c2 =
            reinterpret_cast<const float2*>(coef + ((size_t)bt * NDF + f) * (2 * NO));

        // coef is read exactly once -> evict-first
        const float2 p0 = __ldcs(c2 + 0);
        const float2 p1 = __ldcs(c2 + 1);
        const float2 p2 = __ldcs(c2 + 2);
        const float2 p3 = __ldcs(c2 + 3);
        const float2 p4 = __ldcs(c2 + 4);
        const float cr[NO] = {p0.x, p0.y, p1.x, p1.y, p2.x};
        const float ci[NO] = {p2.y, p3.x, p3.y, p4.x, p4.y};

        float fr = 0.f, fi = 0.f;
        #pragma unroll
        for (int k = 0; k < NO; ++k) {
            const int tk = t - (NO - 1) + k;
            float2 x = make_float2(0.f, 0.f);
            if (tk >= 0)      // taps are reused 5x across rows: default (cache in L2)
                x = spec2[((size_t)(bt - (NO - 1) + k)) * F_DIM + f];
            fr += x.x * cr[k] - x.y * ci[k];
            fi += x.x * ci[k] + x.y * cr[k];
        }
        out2[row + f] = make_float2(fr, fi);
    } else {
        // ---- Copy path: bins [96,481) = 192 float4 + 1 float2, single-use ----
        const int ct = tid - NDF;                  // 0..159
        const bool odd = (bt & 1);
        const size_t v4base = (row + NDF + (odd ? 1 : 0)) >> 1;

        {
            const size_t i4 = v4base + ct;
            __stcs(out4 + i4, __ldcs(spec4 + i4));
        }
        if (ct < 32) {
            const size_t i4 = v4base + 160 + ct;
            __stcs(out4 + i4, __ldcs(spec4 + i4));
        }
        if (ct == 32) {
            const size_t i2 = row + (odd ? NDF : (F_DIM - 1));
            __stcs(out2 + i2, __ldcs(spec2 + i2));
        }
    }
}

extern "C" void kernel_launch(void* const* d_in, const int* in_sizes, int n_in,
                              void* d_out, int out_size)
{
    const float* spec = (const float*)d_in[0];
    const float* coef = (const float*)d_in[1];
    float* out        = (float*)d_out;

    df_kernel<<<8 * T_DIM, 256>>>(spec, coef, out);
}

// round 6
// speedup vs baseline: 1.0474x; 1.0474x over previous
#include <cuda_runtime.h>

// DfOp: complex order-5 causal FIR on first 96 freq bins, copy the rest.
// spec: (B=8, T=3000, F=481, 2) f32 ; coef: (B=8, T=3000, 96, 10) f32
//
// R6 = R4 (champion; streaming hints of R5 reverted) with two rows fused per
// 512-thread block to halve block-scheduling churn. Per-thread work and
// memory access pattern are byte-identical to R4.

#define T_DIM 3000
#define F_DIM 481
#define NDF   96
#define NO    5

__global__ __launch_bounds__(512) void df_kernel(
    const float* __restrict__ spec,
    const float* __restrict__ coef,
    float* __restrict__ out)
{
    // two rows per block: row = 2*bid + (tid>=256)
    const int half = threadIdx.x >> 8;              // 0 or 1
    const int bt   = blockIdx.x * 2 + half;         // row = b*T + t
    const int t    = bt % T_DIM;
    const int tid  = threadIdx.x & 255;             // 0..255 within the row

    const float2* __restrict__ spec2 = reinterpret_cast<const float2*>(spec);
    const float4* __restrict__ spec4 = reinterpret_cast<const float4*>(spec);
    float2* __restrict__ out2 = reinterpret_cast<float2*>(out);
    float4* __restrict__ out4 = reinterpret_cast<float4*>(out);

    const size_t row = (size_t)bt * F_DIM;          // float2 units

    if (tid < NDF) {
        // ---- DF path: one bin per thread ----
        const int f = tid;
        const float2* __restrict__ c2 =
            reinterpret_cast<const float2*>(coef + ((size_t)bt * NDF + f) * (2 * NO));
        const float2 p0 = c2[0], p1 = c2[1], p2 = c2[2], p3 = c2[3], p4 = c2[4];
        const float cr[NO] = {p0.x, p0.y, p1.x, p1.y, p2.x};
        const float ci[NO] = {p2.y, p3.x, p3.y, p4.x, p4.y};

        float fr = 0.f, fi = 0.f;
        #pragma unroll
        for (int k = 0; k < NO; ++k) {
            const int tk = t - (NO - 1) + k;
            float2 x = make_float2(0.f, 0.f);
            if (tk >= 0)
                x = spec2[((size_t)(bt - (NO - 1) + k)) * F_DIM + f];
            fr += x.x * cr[k] - x.y * ci[k];
            fi += x.x * ci[k] + x.y * cr[k];
        }
        out2[row + f] = make_float2(fr, fi);
    } else {
        // ---- Copy path: bins [96,481) = 192 float4 + 1 float2 per row ----
        const int ct = tid - NDF;                   // 0..159
        const bool odd = (bt & 1);
        const size_t v4base = (row + NDF + (odd ? 1 : 0)) >> 1;

        {
            const size_t i4 = v4base + ct;
            out4[i4] = spec4[i4];
        }
        if (ct < 32) {
            const size_t i4 = v4base + 160 + ct;
            out4[i4] = spec4[i4];
        }
        if (ct == 32) {
            const size_t i2 = row + (odd ? NDF : (F_DIM - 1));
            out2[i2] = spec2[i2];
        }
    }
}

extern "C" void kernel_launch(void* const* d_in, const int* in_sizes, int n_in,
                              void* d_out, int out_size)
{
    const float* spec = (const float*)d_in[0];
    const float* coef = (const float*)d_in[1];
    float* out        = (float*)d_out;

    df_kernel<<<(8 * T_DIM) / 2, 512>>>(spec, coef, out);
}